// round 6
// baseline (speedup 1.0000x reference)
#include <cuda_runtime.h>
#include <cuda_bf16.h>
#include <math.h>

#define N_NODES 100000
#define N_EDGES 3200000
#define N_GRAPHS 64
#define F 16
#define NB ((N_NODES + 255) / 256)   // 391 blocks of 256

// ---------------- scratch (static device memory; no allocation) ----------------
__device__ int    d_deg[N_NODES];        // out-degree over row (source)
__device__ int    d_cnt[N_NODES];        // in-count over col (target)
__device__ int    d_off[N_NODES];        // CSR offsets
__device__ int    d_cursor[N_NODES];     // scatter cursors
__device__ int    d_total;               // running base for block offsets
__device__ int    d_done;                // pull2 completion counter
__device__ int2   d_csr[N_EDGES];        // {row, nr_as_float} grouped by col
__device__ float  d_dis[N_NODES];        // deg_inv_sqrt
__device__ float  d_cinv[N_NODES];       // 1/max(cnt,1)
__device__ float4 d_x4[N_NODES];         // padded node features
__device__ float2 d_zea[N_NODES];        // per-node Σ nr*ea (layer-independent)
__device__ float  d_h[N_NODES * F];      // layer-1 output
__device__ float  d_gsum[N_GRAPHS * F];  // pooled sums
__device__ int    d_gcnt[N_GRAPHS];      // nodes per graph

// ---------------- kernels ----------------

__global__ void k_init() {
    int i = blockIdx.x * blockDim.x + threadIdx.x;
    if (i < N_NODES) {
        d_deg[i] = 0;
        d_cnt[i] = 0;
        d_zea[i] = make_float2(0.0f, 0.0f);
    }
    if (i < N_GRAPHS * F) d_gsum[i] = 0.0f;
    if (i < N_GRAPHS) d_gcnt[i] = 0;
    if (i == 0) { d_total = 0; d_done = 0; }
}

// histograms over int32 edge index
__global__ void k_hist(const int* __restrict__ ei) {
    int e = blockIdx.x * blockDim.x + threadIdx.x;
    if (e >= N_EDGES) return;
    atomicAdd(&d_deg[ei[e]], 1);
    atomicAdd(&d_cnt[ei[N_EDGES + e]], 1);
}

// offsets via local scan + atomic block base (order-free), fused finalize
__global__ void k_off(const float* __restrict__ x) {
    __shared__ int sm[256];
    __shared__ int base_sh;
    int t = threadIdx.x;
    int n = blockIdx.x * 256 + t;
    int c = (n < N_NODES) ? d_cnt[n] : 0;
    sm[t] = c;
    __syncthreads();
    for (int off = 1; off < 256; off <<= 1) {
        int v = (t >= off) ? sm[t - off] : 0;
        __syncthreads();
        sm[t] += v;
        __syncthreads();
    }
    if (t == 255) base_sh = atomicAdd(&d_total, sm[255]);
    __syncthreads();
    if (n < N_NODES) {
        int o = base_sh + sm[t] - c;   // exclusive within block + block base
        d_off[n] = o;
        d_cursor[n] = o;
        int dg = d_deg[n];
        d_dis[n] = (dg > 0) ? rsqrtf((float)dg) : 0.0f;
        d_cinv[n] = 1.0f / (float)(c > 0 ? c : 1);
        d_x4[n] = make_float4(x[n * 3 + 0], x[n * 3 + 1], x[n * 3 + 2], 0.0f);
    }
}

// scatter edges into slim CSR; fold nr*ea straight into d_zea via REDG
__global__ void k_scatter(const int* __restrict__ ei, const float* __restrict__ ea) {
    int e = blockIdx.x * blockDim.x + threadIdx.x;
    if (e >= N_EDGES) return;
    int r = ei[e];
    int c = ei[N_EDGES + e];
    float nr = __ldg(&d_dis[r]) * __ldg(&d_dis[c]);
    float2 eav = __ldg(&((const float2*)ea)[e]);
    int pos = atomicAdd(&d_cursor[c], 1);
    d_csr[pos] = make_int2(r, __float_as_int(nr));
    atomicAdd(&d_zea[c].x, nr * eav.x);
    atomicAdd(&d_zea[c].y, nr * eav.y);
}

// layer-1 pull (warp per node) + fused node update:
// z = [Σ nr*x[r] (3), zea (2)];  h = relu(x@Wc1+bc1 + (z@Wn1)*cinv)
__global__ void k_pull1(const float* __restrict__ Wn1,
                        const float* __restrict__ Wc1,
                        const float* __restrict__ bc1) {
    int n = (blockIdx.x * blockDim.x + threadIdx.x) >> 5;
    if (n >= N_NODES) return;
    int lane = threadIdx.x & 31;
    int start = d_off[n];
    int end = start + d_cnt[n];
    float a0 = 0.f, a1 = 0.f, a2 = 0.f;
    for (int i = start + lane; i < end; i += 32) {
        int2 en = d_csr[i];
        float nr = __int_as_float(en.y);
        float4 xv = __ldg(&d_x4[en.x]);
        a0 += nr * xv.x;
        a1 += nr * xv.y;
        a2 += nr * xv.z;
    }
#pragma unroll
    for (int o = 16; o; o >>= 1) {
        a0 += __shfl_xor_sync(0xffffffffu, a0, o);
        a1 += __shfl_xor_sync(0xffffffffu, a1, o);
        a2 += __shfl_xor_sync(0xffffffffu, a2, o);
    }
    if (lane < F) {
        int j = lane;
        float ci = d_cinv[n];
        float2 zea = __ldg(&d_zea[n]);
        float aggr = (a0 * __ldg(&Wn1[0 * F + j]) + a1 * __ldg(&Wn1[1 * F + j]) +
                      a2 * __ldg(&Wn1[2 * F + j]) + zea.x * __ldg(&Wn1[3 * F + j]) +
                      zea.y * __ldg(&Wn1[4 * F + j])) * ci;
        float4 xv = __ldg(&d_x4[n]);
        float cent = __ldg(&bc1[j]) + xv.x * __ldg(&Wc1[0 * F + j]) +
                     xv.y * __ldg(&Wc1[1 * F + j]) + xv.z * __ldg(&Wc1[2 * F + j]);
        d_h[n * F + j] = fmaxf(cent + aggr, 0.0f);
    }
}

// layer-2 pull + node update + graph pooling + (last block) head MLP
__global__ void k_pull2(const float* __restrict__ Wn2,
                        const float* __restrict__ Wc2,
                        const float* __restrict__ bc2,
                        const int* __restrict__ batch,
                        const float* __restrict__ Wl1, const float* __restrict__ bl1,
                        const float* __restrict__ Wl2, const float* __restrict__ bl2,
                        float* __restrict__ out) {
    __shared__ int s_last;
    int n = (blockIdx.x * blockDim.x + threadIdx.x) >> 5;
    int lane = threadIdx.x & 31;
    if (n < N_NODES) {
        int start = d_off[n];
        int end = start + d_cnt[n];
        float acc[F];
#pragma unroll
        for (int k = 0; k < F; k++) acc[k] = 0.0f;
        for (int i = start + lane; i < end; i += 32) {
            int2 en = d_csr[i];
            float nr = __int_as_float(en.y);
            const float4* hp = (const float4*)&d_h[en.x * F];
            float4 v0 = __ldg(&hp[0]), v1 = __ldg(&hp[1]), v2 = __ldg(&hp[2]), v3 = __ldg(&hp[3]);
            acc[0]  += nr * v0.x; acc[1]  += nr * v0.y; acc[2]  += nr * v0.z; acc[3]  += nr * v0.w;
            acc[4]  += nr * v1.x; acc[5]  += nr * v1.y; acc[6]  += nr * v1.z; acc[7]  += nr * v1.w;
            acc[8]  += nr * v2.x; acc[9]  += nr * v2.y; acc[10] += nr * v2.z; acc[11] += nr * v2.w;
            acc[12] += nr * v3.x; acc[13] += nr * v3.y; acc[14] += nr * v3.z; acc[15] += nr * v3.w;
        }
#pragma unroll
        for (int o = 16; o; o >>= 1) {
#pragma unroll
            for (int k = 0; k < F; k++) acc[k] += __shfl_xor_sync(0xffffffffu, acc[k], o);
        }
        int g = __ldg(&batch[n]);
        if (lane == 16) atomicAdd(&d_gcnt[g], 1);
        if (lane < F) {
            int j = lane;
            float ci = d_cinv[n];
            float2 zea = __ldg(&d_zea[n]);
            float aggr = zea.x * __ldg(&Wn2[16 * F + j]) + zea.y * __ldg(&Wn2[17 * F + j]);
#pragma unroll
            for (int k = 0; k < F; k++) aggr += acc[k] * __ldg(&Wn2[k * F + j]);
            aggr *= ci;
            float cent = __ldg(&bc2[j]);
            const float* hn = &d_h[n * F];
#pragma unroll
            for (int k = 0; k < F; k++) cent += hn[k] * __ldg(&Wc2[k * F + j]);
            float v = fmaxf(cent + aggr, 0.0f);
            atomicAdd(&d_gsum[g * F + j], v);
        }
    }
    // ---- last-block-done head ----
    __syncthreads();
    if (threadIdx.x == 0) {
        __threadfence();
        int prev = atomicAdd(&d_done, 1);
        s_last = (prev == (int)gridDim.x - 1);
    }
    __syncthreads();
    if (s_last) {
        __threadfence();
        int g = threadIdx.x;
        if (g < N_GRAPHS) {
            int c = d_gcnt[g];
            float inv = 1.0f / (float)(c > 0 ? c : 1);
            float gm[F];
#pragma unroll
            for (int k = 0; k < F; k++) gm[k] = d_gsum[g * F + k] * inv;
            float t[F];
#pragma unroll
            for (int j = 0; j < F; j++) {
                float a = __ldg(&bl1[j]);
#pragma unroll
                for (int k = 0; k < F; k++) a += gm[k] * __ldg(&Wl1[k * F + j]);
                t[j] = fmaxf(a, 0.0f);
            }
#pragma unroll
            for (int o = 0; o < 2; o++) {
                float a = __ldg(&bl2[o]);
#pragma unroll
                for (int j = 0; j < F; j++) a += t[j] * __ldg(&Wl2[j * 2 + o]);
                out[g * 2 + o] = a;
            }
        }
    }
}

// ---------------- launch ----------------
extern "C" void kernel_launch(void* const* d_in, const int* in_sizes, int n_in,
                              void* d_out, int out_size) {
    const float* x     = (const float*)d_in[0];
    const int*   ei    = (const int*)d_in[1];
    const float* ea    = (const float*)d_in[2];
    const int*   batch = (const int*)d_in[3];
    const float* Wc1 = (const float*)d_in[4];
    const float* bc1 = (const float*)d_in[5];
    const float* Wn1 = (const float*)d_in[6];
    const float* Wc2 = (const float*)d_in[7];
    const float* bc2 = (const float*)d_in[8];
    const float* Wn2 = (const float*)d_in[9];
    const float* Wl1 = (const float*)d_in[10];
    const float* bl1 = (const float*)d_in[11];
    const float* Wl2 = (const float*)d_in[12];
    const float* bl2 = (const float*)d_in[13];
    float* out = (float*)d_out;

    const int T = 256;
    int eb = (N_EDGES + T - 1) / T;
    int wb = (N_NODES * 32 + T - 1) / T;   // warp-per-node grids (=12500)

    k_init<<<NB, T>>>();
    k_hist<<<eb, T>>>(ei);
    k_off<<<NB, T>>>(x);
    k_scatter<<<eb, T>>>(ei, ea);
    k_pull1<<<wb, T>>>(Wn1, Wc1, bc1);
    k_pull2<<<wb, T>>>(Wn2, Wc2, bc2, batch, Wl1, bl1, Wl2, bl2, out);
}

// round 7
// speedup vs baseline: 1.0712x; 1.0712x over previous
#include <cuda_runtime.h>
#include <cuda_bf16.h>
#include <math.h>

#define N_NODES 100000
#define N_EDGES 3200000
#define N_GRAPHS 64
#define F 16
#define NB ((N_NODES + 255) / 256)   // 391 blocks of 256

// ---------------- scratch (static device memory; no allocation) ----------------
__device__ int    d_deg[N_NODES];        // out-degree over row (source)
__device__ int    d_cnt[N_NODES];        // in-count over col (target)
__device__ int    d_off[N_NODES];        // CSR offsets
__device__ int    d_cursor[N_NODES];     // scatter cursors
__device__ int    d_total;               // running base for block offsets
__device__ int    d_done;                // pull2 completion counter
__device__ float4 d_csr[N_EDGES];        // {row_as_float, nr, nr*ea.x, nr*ea.y} grouped by col
__device__ float  d_dis[N_NODES];        // deg_inv_sqrt
__device__ float  d_cinv[N_NODES];       // 1/max(cnt,1)
__device__ float4 d_x4[N_NODES];         // padded node features
__device__ float2 d_zea[N_NODES];        // per-node Σ nr*ea (layer-independent)
__device__ float  d_h[N_NODES * F];      // layer-1 output
__device__ float  d_gsum[N_GRAPHS * F];  // pooled sums
__device__ int    d_gcnt[N_GRAPHS];      // nodes per graph

// ---------------- kernels ----------------

__global__ void k_init() {
    int i = blockIdx.x * blockDim.x + threadIdx.x;
    if (i < N_NODES) { d_deg[i] = 0; d_cnt[i] = 0; }
    if (i < N_GRAPHS * F) d_gsum[i] = 0.0f;
    if (i < N_GRAPHS) d_gcnt[i] = 0;
    if (i == 0) { d_total = 0; d_done = 0; }
}

// histograms over int32 edge index
__global__ void k_hist(const int* __restrict__ ei) {
    int e = blockIdx.x * blockDim.x + threadIdx.x;
    if (e >= N_EDGES) return;
    atomicAdd(&d_deg[ei[e]], 1);
    atomicAdd(&d_cnt[ei[N_EDGES + e]], 1);
}

// offsets via local scan + atomic block base (order-free), fused finalize
__global__ void k_off(const float* __restrict__ x) {
    __shared__ int sm[256];
    __shared__ int base_sh;
    int t = threadIdx.x;
    int n = blockIdx.x * 256 + t;
    int c = (n < N_NODES) ? d_cnt[n] : 0;
    sm[t] = c;
    __syncthreads();
    for (int off = 1; off < 256; off <<= 1) {
        int v = (t >= off) ? sm[t - off] : 0;
        __syncthreads();
        sm[t] += v;
        __syncthreads();
    }
    if (t == 255) base_sh = atomicAdd(&d_total, sm[255]);
    __syncthreads();
    if (n < N_NODES) {
        int o = base_sh + sm[t] - c;   // exclusive within block + block base
        d_off[n] = o;
        d_cursor[n] = o;
        int dg = d_deg[n];
        d_dis[n] = (dg > 0) ? rsqrtf((float)dg) : 0.0f;
        d_cinv[n] = 1.0f / (float)(c > 0 ? c : 1);
        d_x4[n] = make_float4(x[n * 3 + 0], x[n * 3 + 1], x[n * 3 + 2], 0.0f);
    }
}

// scatter edges into fat CSR entries grouped by target (col); one STG.128 + one cursor atomic
__global__ void k_scatter(const int* __restrict__ ei, const float* __restrict__ ea) {
    int e = blockIdx.x * blockDim.x + threadIdx.x;
    if (e >= N_EDGES) return;
    int r = ei[e];
    int c = ei[N_EDGES + e];
    float nr = __ldg(&d_dis[r]) * __ldg(&d_dis[c]);
    float2 eav = __ldg(&((const float2*)ea)[e]);
    int pos = atomicAdd(&d_cursor[c], 1);
    d_csr[pos] = make_float4(__int_as_float(r), nr, nr * eav.x, nr * eav.y);
}

// layer-1 pull (warp per node) + fused node update:
// z = [Σ nr*x[r] (3), Σ nr*ea (2)];  h = relu(x@Wc1+bc1 + (z@Wn1)*cinv)
__global__ void k_pull1(const float* __restrict__ Wn1,
                        const float* __restrict__ Wc1,
                        const float* __restrict__ bc1) {
    int n = (blockIdx.x * blockDim.x + threadIdx.x) >> 5;
    if (n >= N_NODES) return;
    int lane = threadIdx.x & 31;
    int start = d_off[n];
    int end = start + d_cnt[n];
    float a0 = 0.f, a1 = 0.f, a2 = 0.f, a3 = 0.f, a4 = 0.f;
    for (int i = start + lane; i < end; i += 32) {
        float4 en = d_csr[i];
        int r = __float_as_int(en.x);
        float nr = en.y;
        float4 xv = __ldg(&d_x4[r]);
        a0 += nr * xv.x;
        a1 += nr * xv.y;
        a2 += nr * xv.z;
        a3 += en.z;
        a4 += en.w;
    }
#pragma unroll
    for (int o = 16; o; o >>= 1) {
        a0 += __shfl_xor_sync(0xffffffffu, a0, o);
        a1 += __shfl_xor_sync(0xffffffffu, a1, o);
        a2 += __shfl_xor_sync(0xffffffffu, a2, o);
        a3 += __shfl_xor_sync(0xffffffffu, a3, o);
        a4 += __shfl_xor_sync(0xffffffffu, a4, o);
    }
    if (lane == 0) d_zea[n] = make_float2(a3, a4);
    if (lane < F) {
        int j = lane;
        float ci = d_cinv[n];
        float aggr = (a0 * __ldg(&Wn1[0 * F + j]) + a1 * __ldg(&Wn1[1 * F + j]) +
                      a2 * __ldg(&Wn1[2 * F + j]) + a3 * __ldg(&Wn1[3 * F + j]) +
                      a4 * __ldg(&Wn1[4 * F + j])) * ci;
        float4 xv = __ldg(&d_x4[n]);
        float cent = __ldg(&bc1[j]) + xv.x * __ldg(&Wc1[0 * F + j]) +
                     xv.y * __ldg(&Wc1[1 * F + j]) + xv.z * __ldg(&Wc1[2 * F + j]);
        d_h[n * F + j] = fmaxf(cent + aggr, 0.0f);
    }
}

// layer-2 pull + node update + graph pooling + (last block) head MLP
__global__ void k_pull2(const float* __restrict__ Wn2,
                        const float* __restrict__ Wc2,
                        const float* __restrict__ bc2,
                        const int* __restrict__ batch,
                        const float* __restrict__ Wl1, const float* __restrict__ bl1,
                        const float* __restrict__ Wl2, const float* __restrict__ bl2,
                        float* __restrict__ out) {
    __shared__ int s_last;
    int n = (blockIdx.x * blockDim.x + threadIdx.x) >> 5;
    int lane = threadIdx.x & 31;
    if (n < N_NODES) {
        int start = d_off[n];
        int end = start + d_cnt[n];
        float acc[F];
#pragma unroll
        for (int k = 0; k < F; k++) acc[k] = 0.0f;
        for (int i = start + lane; i < end; i += 32) {
            float4 en = d_csr[i];
            int r = __float_as_int(en.x);
            float nr = en.y;
            const float4* hp = (const float4*)&d_h[r * F];
            float4 v0 = __ldg(&hp[0]), v1 = __ldg(&hp[1]), v2 = __ldg(&hp[2]), v3 = __ldg(&hp[3]);
            acc[0]  += nr * v0.x; acc[1]  += nr * v0.y; acc[2]  += nr * v0.z; acc[3]  += nr * v0.w;
            acc[4]  += nr * v1.x; acc[5]  += nr * v1.y; acc[6]  += nr * v1.z; acc[7]  += nr * v1.w;
            acc[8]  += nr * v2.x; acc[9]  += nr * v2.y; acc[10] += nr * v2.z; acc[11] += nr * v2.w;
            acc[12] += nr * v3.x; acc[13] += nr * v3.y; acc[14] += nr * v3.z; acc[15] += nr * v3.w;
        }
#pragma unroll
        for (int o = 16; o; o >>= 1) {
#pragma unroll
            for (int k = 0; k < F; k++) acc[k] += __shfl_xor_sync(0xffffffffu, acc[k], o);
        }
        int g = __ldg(&batch[n]);
        if (lane == 16) atomicAdd(&d_gcnt[g], 1);
        if (lane < F) {
            int j = lane;
            float ci = d_cinv[n];
            float2 zea = d_zea[n];
            float aggr = zea.x * __ldg(&Wn2[16 * F + j]) + zea.y * __ldg(&Wn2[17 * F + j]);
#pragma unroll
            for (int k = 0; k < F; k++) aggr += acc[k] * __ldg(&Wn2[k * F + j]);
            aggr *= ci;
            float cent = __ldg(&bc2[j]);
            const float* hn = &d_h[n * F];
#pragma unroll
            for (int k = 0; k < F; k++) cent += hn[k] * __ldg(&Wc2[k * F + j]);
            float v = fmaxf(cent + aggr, 0.0f);
            atomicAdd(&d_gsum[g * F + j], v);
        }
    }
    // ---- last-block-done head ----
    __syncthreads();
    if (threadIdx.x == 0) {
        __threadfence();
        int prev = atomicAdd(&d_done, 1);
        s_last = (prev == (int)gridDim.x - 1);
    }
    __syncthreads();
    if (s_last) {
        __threadfence();
        int g = threadIdx.x;
        if (g < N_GRAPHS) {
            int c = d_gcnt[g];
            float inv = 1.0f / (float)(c > 0 ? c : 1);
            float gm[F];
#pragma unroll
            for (int k = 0; k < F; k++) gm[k] = d_gsum[g * F + k] * inv;
            float t[F];
#pragma unroll
            for (int j = 0; j < F; j++) {
                float a = __ldg(&bl1[j]);
#pragma unroll
                for (int k = 0; k < F; k++) a += gm[k] * __ldg(&Wl1[k * F + j]);
                t[j] = fmaxf(a, 0.0f);
            }
#pragma unroll
            for (int o = 0; o < 2; o++) {
                float a = __ldg(&bl2[o]);
#pragma unroll
                for (int j = 0; j < F; j++) a += t[j] * __ldg(&Wl2[j * 2 + o]);
                out[g * 2 + o] = a;
            }
        }
    }
}

// ---------------- launch ----------------
extern "C" void kernel_launch(void* const* d_in, const int* in_sizes, int n_in,
                              void* d_out, int out_size) {
    const float* x     = (const float*)d_in[0];
    const int*   ei    = (const int*)d_in[1];
    const float* ea    = (const float*)d_in[2];
    const int*   batch = (const int*)d_in[3];
    const float* Wc1 = (const float*)d_in[4];
    const float* bc1 = (const float*)d_in[5];
    const float* Wn1 = (const float*)d_in[6];
    const float* Wc2 = (const float*)d_in[7];
    const float* bc2 = (const float*)d_in[8];
    const float* Wn2 = (const float*)d_in[9];
    const float* Wl1 = (const float*)d_in[10];
    const float* bl1 = (const float*)d_in[11];
    const float* Wl2 = (const float*)d_in[12];
    const float* bl2 = (const float*)d_in[13];
    float* out = (float*)d_out;

    const int T = 256;
    int eb = (N_EDGES + T - 1) / T;
    int wb = (N_NODES * 32 + T - 1) / T;   // warp-per-node grids (=12500)

    k_init<<<NB, T>>>();
    k_hist<<<eb, T>>>(ei);
    k_off<<<NB, T>>>(x);
    k_scatter<<<eb, T>>>(ei, ea);
    k_pull1<<<wb, T>>>(Wn1, Wc1, bc1);
    k_pull2<<<wb, T>>>(Wn2, Wc2, bc2, batch, Wl1, bl1, Wl2, bl2, out);
}

// round 8
// speedup vs baseline: 1.1738x; 1.0958x over previous
#include <cuda_runtime.h>
#include <cuda_bf16.h>
#include <math.h>

#define N_NODES 100000
#define N_EDGES 3200000
#define N_GRAPHS 64
#define F 16
#define NB ((N_NODES + 255) / 256)   // 391 blocks of 256

// ---------------- scratch (static device memory; no allocation) ----------------
__device__ int    d_deg[N_NODES];        // out-degree over row (source)
__device__ int    d_cnt[N_NODES];        // in-count over col (target)
__device__ int    d_off[N_NODES];        // CSR offsets
__device__ int    d_cursor[N_NODES];     // scatter cursors
__device__ int    d_total;               // running base for block offsets
__device__ float4 d_csr[N_EDGES];        // {row_as_float, ea.x, ea.y, nr(filled by pull1)}
__device__ float  d_dis[N_NODES];        // deg_inv_sqrt
__device__ float  d_cinv[N_NODES];       // 1/max(cnt,1)
__device__ float4 d_x4[N_NODES];         // {x0, x1, x2, dis}
__device__ float2 d_zea[N_NODES];        // per-node Σ nr*ea (layer-independent)
__device__ float  d_h[N_NODES * F];      // layer-1 output
__device__ float  d_gsum[N_GRAPHS * F];  // pooled sums
__device__ int    d_gcnt[N_GRAPHS];      // nodes per graph

// ---------------- kernels ----------------

__global__ void k_init() {
    int i = blockIdx.x * blockDim.x + threadIdx.x;
    if (i < N_NODES) { d_deg[i] = 0; d_cnt[i] = 0; }
    if (i < N_GRAPHS * F) d_gsum[i] = 0.0f;
    if (i < N_GRAPHS) d_gcnt[i] = 0;
    if (i == 0) { d_total = 0; }
}

// histograms over int32 edge index
__global__ void k_hist(const int* __restrict__ ei) {
    int e = blockIdx.x * blockDim.x + threadIdx.x;
    if (e >= N_EDGES) return;
    atomicAdd(&d_deg[ei[e]], 1);
    atomicAdd(&d_cnt[ei[N_EDGES + e]], 1);
}

// offsets via local scan + atomic block base (order-free), fused finalize
__global__ void k_off(const float* __restrict__ x) {
    __shared__ int sm[256];
    __shared__ int base_sh;
    int t = threadIdx.x;
    int n = blockIdx.x * 256 + t;
    int c = (n < N_NODES) ? d_cnt[n] : 0;
    sm[t] = c;
    __syncthreads();
    for (int off = 1; off < 256; off <<= 1) {
        int v = (t >= off) ? sm[t - off] : 0;
        __syncthreads();
        sm[t] += v;
        __syncthreads();
    }
    if (t == 255) base_sh = atomicAdd(&d_total, sm[255]);
    __syncthreads();
    if (n < N_NODES) {
        int o = base_sh + sm[t] - c;   // exclusive within block + block base
        d_off[n] = o;
        d_cursor[n] = o;
        int dg = d_deg[n];
        float dis = (dg > 0) ? rsqrtf((float)dg) : 0.0f;
        d_dis[n] = dis;
        d_cinv[n] = 1.0f / (float)(c > 0 ? c : 1);
        d_x4[n] = make_float4(x[n * 3 + 0], x[n * 3 + 1], x[n * 3 + 2], dis);
    }
}

// scatter edges grouped by target; NO norm computation (deferred to pull1)
__global__ void k_scatter(const int* __restrict__ ei, const float* __restrict__ ea) {
    int e = blockIdx.x * blockDim.x + threadIdx.x;
    if (e >= N_EDGES) return;
    int r = ei[e];
    int c = ei[N_EDGES + e];
    float2 eav = __ldg(&((const float2*)ea)[e]);
    int pos = atomicAdd(&d_cursor[c], 1);
    d_csr[pos] = make_float4(__int_as_float(r), eav.x, eav.y, 0.0f);
}

// layer-1 pull (warp per node): computes nr from x4[r].w, writes nr back to CSR
// z = [Σ nr*x[r] (3), Σ nr*ea (2)];  h = relu(x@Wc1+bc1 + (z@Wn1)*cinv)
__global__ void k_pull1(const float* __restrict__ Wn1,
                        const float* __restrict__ Wc1,
                        const float* __restrict__ bc1) {
    int n = (blockIdx.x * blockDim.x + threadIdx.x) >> 5;
    if (n >= N_NODES) return;
    int lane = threadIdx.x & 31;
    int start = d_off[n];
    int end = start + d_cnt[n];
    float disc = d_dis[n];
    float a0 = 0.f, a1 = 0.f, a2 = 0.f, a3 = 0.f, a4 = 0.f;
    for (int i = start + lane; i < end; i += 32) {
        float4 en = d_csr[i];
        int r = __float_as_int(en.x);
        float4 xv = __ldg(&d_x4[r]);
        float nr = xv.w * disc;
        d_csr[i].w = nr;              // stash for pull2 (coalesced, line is L2-hot)
        a0 += nr * xv.x;
        a1 += nr * xv.y;
        a2 += nr * xv.z;
        a3 += nr * en.y;
        a4 += nr * en.z;
    }
#pragma unroll
    for (int o = 16; o; o >>= 1) {
        a0 += __shfl_xor_sync(0xffffffffu, a0, o);
        a1 += __shfl_xor_sync(0xffffffffu, a1, o);
        a2 += __shfl_xor_sync(0xffffffffu, a2, o);
        a3 += __shfl_xor_sync(0xffffffffu, a3, o);
        a4 += __shfl_xor_sync(0xffffffffu, a4, o);
    }
    if (lane == 0) d_zea[n] = make_float2(a3, a4);
    if (lane < F) {
        int j = lane;
        float ci = d_cinv[n];
        float aggr = (a0 * __ldg(&Wn1[0 * F + j]) + a1 * __ldg(&Wn1[1 * F + j]) +
                      a2 * __ldg(&Wn1[2 * F + j]) + a3 * __ldg(&Wn1[3 * F + j]) +
                      a4 * __ldg(&Wn1[4 * F + j])) * ci;
        float4 xv = __ldg(&d_x4[n]);
        float cent = __ldg(&bc1[j]) + xv.x * __ldg(&Wc1[0 * F + j]) +
                     xv.y * __ldg(&Wc1[1 * F + j]) + xv.z * __ldg(&Wc1[2 * F + j]);
        d_h[n * F + j] = fmaxf(cent + aggr, 0.0f);
    }
}

// layer-2 pull + node update + graph pooling (no head here — keep regs low)
__global__ void k_pull2(const float* __restrict__ Wn2,
                        const float* __restrict__ Wc2,
                        const float* __restrict__ bc2,
                        const int* __restrict__ batch) {
    int n = (blockIdx.x * blockDim.x + threadIdx.x) >> 5;
    if (n >= N_NODES) return;
    int lane = threadIdx.x & 31;
    int start = d_off[n];
    int end = start + d_cnt[n];
    float acc[F];
#pragma unroll
    for (int k = 0; k < F; k++) acc[k] = 0.0f;
    for (int i = start + lane; i < end; i += 32) {
        float4 en = d_csr[i];
        int r = __float_as_int(en.x);
        float nr = en.w;
        const float4* hp = (const float4*)&d_h[r * F];
        float4 v0 = __ldg(&hp[0]), v1 = __ldg(&hp[1]), v2 = __ldg(&hp[2]), v3 = __ldg(&hp[3]);
        acc[0]  += nr * v0.x; acc[1]  += nr * v0.y; acc[2]  += nr * v0.z; acc[3]  += nr * v0.w;
        acc[4]  += nr * v1.x; acc[5]  += nr * v1.y; acc[6]  += nr * v1.z; acc[7]  += nr * v1.w;
        acc[8]  += nr * v2.x; acc[9]  += nr * v2.y; acc[10] += nr * v2.z; acc[11] += nr * v2.w;
        acc[12] += nr * v3.x; acc[13] += nr * v3.y; acc[14] += nr * v3.z; acc[15] += nr * v3.w;
    }
#pragma unroll
    for (int o = 16; o; o >>= 1) {
#pragma unroll
        for (int k = 0; k < F; k++) acc[k] += __shfl_xor_sync(0xffffffffu, acc[k], o);
    }
    int g = __ldg(&batch[n]);
    if (lane == 16) atomicAdd(&d_gcnt[g], 1);
    if (lane < F) {
        int j = lane;
        float ci = d_cinv[n];
        float2 zea = d_zea[n];
        float aggr = zea.x * __ldg(&Wn2[16 * F + j]) + zea.y * __ldg(&Wn2[17 * F + j]);
#pragma unroll
        for (int k = 0; k < F; k++) aggr += acc[k] * __ldg(&Wn2[k * F + j]);
        aggr *= ci;
        float cent = __ldg(&bc2[j]);
        const float* hn = &d_h[n * F];
#pragma unroll
        for (int k = 0; k < F; k++) cent += hn[k] * __ldg(&Wc2[k * F + j]);
        float v = fmaxf(cent + aggr, 0.0f);
        atomicAdd(&d_gsum[g * F + j], v);
    }
}

// head MLP (mean + 2-layer MLP)
__global__ void k_head(const float* __restrict__ Wl1, const float* __restrict__ bl1,
                       const float* __restrict__ Wl2, const float* __restrict__ bl2,
                       float* __restrict__ out) {
    int g = threadIdx.x;
    if (g >= N_GRAPHS) return;
    int c = d_gcnt[g];
    float inv = 1.0f / (float)(c > 0 ? c : 1);
    float gm[F];
#pragma unroll
    for (int k = 0; k < F; k++) gm[k] = d_gsum[g * F + k] * inv;
    float t[F];
#pragma unroll
    for (int j = 0; j < F; j++) {
        float a = bl1[j];
#pragma unroll
        for (int k = 0; k < F; k++) a += gm[k] * Wl1[k * F + j];
        t[j] = fmaxf(a, 0.0f);
    }
#pragma unroll
    for (int o = 0; o < 2; o++) {
        float a = bl2[o];
#pragma unroll
        for (int j = 0; j < F; j++) a += t[j] * Wl2[j * 2 + o];
        out[g * 2 + o] = a;
    }
}

// ---------------- launch ----------------
extern "C" void kernel_launch(void* const* d_in, const int* in_sizes, int n_in,
                              void* d_out, int out_size) {
    const float* x     = (const float*)d_in[0];
    const int*   ei    = (const int*)d_in[1];
    const float* ea    = (const float*)d_in[2];
    const int*   batch = (const int*)d_in[3];
    const float* Wc1 = (const float*)d_in[4];
    const float* bc1 = (const float*)d_in[5];
    const float* Wn1 = (const float*)d_in[6];
    const float* Wc2 = (const float*)d_in[7];
    const float* bc2 = (const float*)d_in[8];
    const float* Wn2 = (const float*)d_in[9];
    const float* Wl1 = (const float*)d_in[10];
    const float* bl1 = (const float*)d_in[11];
    const float* Wl2 = (const float*)d_in[12];
    const float* bl2 = (const float*)d_in[13];
    float* out = (float*)d_out;

    const int T = 256;
    int eb = (N_EDGES + T - 1) / T;
    int wb = (N_NODES * 32 + T - 1) / T;   // warp-per-node grids (=12500)

    k_init<<<NB, T>>>();
    k_hist<<<eb, T>>>(ei);
    k_off<<<NB, T>>>(x);
    k_scatter<<<eb, T>>>(ei, ea);
    k_pull1<<<wb, T>>>(Wn1, Wc1, bc1);
    k_pull2<<<wb, T>>>(Wn2, Wc2, bc2, batch);
    k_head<<<1, 64>>>(Wl1, bl1, Wl2, bl2, out);
}

// round 9
// speedup vs baseline: 1.2560x; 1.0701x over previous
#include <cuda_runtime.h>
#include <cuda_bf16.h>
#include <cuda_fp16.h>
#include <math.h>

#define N_NODES 100000
#define N_EDGES 3200000
#define N_GRAPHS 64
#define F 16
#define NB ((N_NODES + 255) / 256)   // 391 blocks of 256

// ---------------- scratch (static device memory; no allocation) ----------------
// Invariant: d_deg, d_cnt, d_gsum, d_gcnt, d_total are ZERO before every launch
// (zero-initialized at load; each launch re-zeroes them after last use).
__device__ int    d_deg[N_NODES];        // out-degree over row (source)
__device__ int    d_cnt[N_NODES];        // in-count over col (target)
__device__ int    d_off[N_NODES];        // CSR offsets
__device__ int    d_cursor[N_NODES];     // scatter cursors
__device__ int    d_total;               // running base for block offsets
__device__ float4 d_csr[N_EDGES];        // {row_as_float, ea.x, ea.y, nr(filled by pull1)}
__device__ float  d_dis[N_NODES];        // deg_inv_sqrt
__device__ float  d_cinv[N_NODES];       // 1/max(cnt,1)
__device__ float4 d_x4[N_NODES];         // {x0, x1, x2, dis}
__device__ float2 d_zea[N_NODES];        // per-node Σ nr*ea (layer-independent)
__device__ float  d_h[N_NODES * F];      // layer-1 output (fp32, center path)
__device__ __half d_hh[N_NODES * F];     // layer-1 output (fp16 shadow, gather path)
__device__ float  d_gsum[N_GRAPHS * F];  // pooled sums
__device__ int    d_gcnt[N_GRAPHS];      // nodes per graph

// ---------------- kernels ----------------

// histograms, 4 edges per thread (batched loads, 8 independent atomics in flight)
__global__ void k_hist(const int* __restrict__ ei) {
    int t = blockIdx.x * blockDim.x + threadIdx.x;
    int e = t * 4;
    if (e >= N_EDGES) return;            // N_EDGES % 4 == 0, no tail
    int4 r4 = *(const int4*)&ei[e];
    int4 c4 = *(const int4*)&ei[N_EDGES + e];
    atomicAdd(&d_deg[r4.x], 1);
    atomicAdd(&d_deg[r4.y], 1);
    atomicAdd(&d_deg[r4.z], 1);
    atomicAdd(&d_deg[r4.w], 1);
    atomicAdd(&d_cnt[c4.x], 1);
    atomicAdd(&d_cnt[c4.y], 1);
    atomicAdd(&d_cnt[c4.z], 1);
    atomicAdd(&d_cnt[c4.w], 1);
}

// offsets via local scan + atomic block base (order-free), fused finalize.
// Also re-zeroes d_deg for the next launch (last consumer).
__global__ void k_off(const float* __restrict__ x) {
    __shared__ int sm[256];
    __shared__ int base_sh;
    int t = threadIdx.x;
    int n = blockIdx.x * 256 + t;
    int c = (n < N_NODES) ? d_cnt[n] : 0;
    sm[t] = c;
    __syncthreads();
    for (int off = 1; off < 256; off <<= 1) {
        int v = (t >= off) ? sm[t - off] : 0;
        __syncthreads();
        sm[t] += v;
        __syncthreads();
    }
    if (t == 255) base_sh = atomicAdd(&d_total, sm[255]);
    __syncthreads();
    if (n < N_NODES) {
        int o = base_sh + sm[t] - c;   // exclusive within block + block base
        d_off[n] = o;
        d_cursor[n] = o;
        int dg = d_deg[n];
        d_deg[n] = 0;                  // restore invariant for next launch
        float dis = (dg > 0) ? rsqrtf((float)dg) : 0.0f;
        d_dis[n] = dis;
        d_cinv[n] = 1.0f / (float)(c > 0 ? c : 1);
        d_x4[n] = make_float4(x[n * 3 + 0], x[n * 3 + 1], x[n * 3 + 2], dis);
    }
}

// scatter edges grouped by target, 4 edges per thread; no norm computation
__global__ void k_scatter(const int* __restrict__ ei, const float* __restrict__ ea) {
    int t = blockIdx.x * blockDim.x + threadIdx.x;
    int e = t * 4;
    if (e >= N_EDGES) return;
    int4 r4 = *(const int4*)&ei[e];
    int4 c4 = *(const int4*)&ei[N_EDGES + e];
    float4 ea01 = __ldg(&((const float4*)ea)[t * 2 + 0]);   // ea[e], ea[e+1]
    float4 ea23 = __ldg(&((const float4*)ea)[t * 2 + 1]);   // ea[e+2], ea[e+3]
    int p0 = atomicAdd(&d_cursor[c4.x], 1);
    int p1 = atomicAdd(&d_cursor[c4.y], 1);
    int p2 = atomicAdd(&d_cursor[c4.z], 1);
    int p3 = atomicAdd(&d_cursor[c4.w], 1);
    d_csr[p0] = make_float4(__int_as_float(r4.x), ea01.x, ea01.y, 0.0f);
    d_csr[p1] = make_float4(__int_as_float(r4.y), ea01.z, ea01.w, 0.0f);
    d_csr[p2] = make_float4(__int_as_float(r4.z), ea23.x, ea23.y, 0.0f);
    d_csr[p3] = make_float4(__int_as_float(r4.w), ea23.z, ea23.w, 0.0f);
}

// layer-1 pull (warp per node): computes nr from x4[r].w, writes nr back to CSR
// z = [Σ nr*x[r] (3), Σ nr*ea (2)];  h = relu(x@Wc1+bc1 + (z@Wn1)*cinv)
__global__ void k_pull1(const float* __restrict__ Wn1,
                        const float* __restrict__ Wc1,
                        const float* __restrict__ bc1) {
    int n = (blockIdx.x * blockDim.x + threadIdx.x) >> 5;
    if (n >= N_NODES) return;
    int lane = threadIdx.x & 31;
    int start = d_off[n];
    int end = start + d_cnt[n];
    float disc = d_dis[n];
    float a0 = 0.f, a1 = 0.f, a2 = 0.f, a3 = 0.f, a4 = 0.f;
    for (int i = start + lane; i < end; i += 32) {
        float4 en = d_csr[i];
        int r = __float_as_int(en.x);
        float4 xv = __ldg(&d_x4[r]);
        float nr = xv.w * disc;
        d_csr[i].w = nr;              // stash for pull2 (coalesced, line is L2-hot)
        a0 += nr * xv.x;
        a1 += nr * xv.y;
        a2 += nr * xv.z;
        a3 += nr * en.y;
        a4 += nr * en.z;
    }
#pragma unroll
    for (int o = 16; o; o >>= 1) {
        a0 += __shfl_xor_sync(0xffffffffu, a0, o);
        a1 += __shfl_xor_sync(0xffffffffu, a1, o);
        a2 += __shfl_xor_sync(0xffffffffu, a2, o);
        a3 += __shfl_xor_sync(0xffffffffu, a3, o);
        a4 += __shfl_xor_sync(0xffffffffu, a4, o);
    }
    if (lane == 0) d_zea[n] = make_float2(a3, a4);
    if (lane < F) {
        int j = lane;
        float ci = d_cinv[n];
        float aggr = (a0 * __ldg(&Wn1[0 * F + j]) + a1 * __ldg(&Wn1[1 * F + j]) +
                      a2 * __ldg(&Wn1[2 * F + j]) + a3 * __ldg(&Wn1[3 * F + j]) +
                      a4 * __ldg(&Wn1[4 * F + j])) * ci;
        float4 xv = __ldg(&d_x4[n]);
        float cent = __ldg(&bc1[j]) + xv.x * __ldg(&Wc1[0 * F + j]) +
                     xv.y * __ldg(&Wc1[1 * F + j]) + xv.z * __ldg(&Wc1[2 * F + j]);
        float v = fmaxf(cent + aggr, 0.0f);
        d_h[n * F + j] = v;
        d_hh[n * F + j] = __float2half(v);
    }
}

// layer-2 pull (fp16 gather) + node update + graph pooling; re-zeroes d_cnt
__global__ void k_pull2(const float* __restrict__ Wn2,
                        const float* __restrict__ Wc2,
                        const float* __restrict__ bc2,
                        const int* __restrict__ batch) {
    int n = (blockIdx.x * blockDim.x + threadIdx.x) >> 5;
    if (n >= N_NODES) return;
    int lane = threadIdx.x & 31;
    int start = d_off[n];
    int cnt = d_cnt[n];
    int end = start + cnt;
    float acc[F];
#pragma unroll
    for (int k = 0; k < F; k++) acc[k] = 0.0f;
    for (int i = start + lane; i < end; i += 32) {
        float4 en = d_csr[i];
        int r = __float_as_int(en.x);
        float nr = en.w;
        const uint4* hp = (const uint4*)&d_hh[r * F];
        uint4 u0 = __ldg(&hp[0]);      // halves 0..7
        uint4 u1 = __ldg(&hp[1]);      // halves 8..15
        const __half2* p0 = (const __half2*)&u0;
        const __half2* p1 = (const __half2*)&u1;
#pragma unroll
        for (int w = 0; w < 4; w++) {
            float2 f = __half22float2(p0[w]);
            acc[2 * w + 0] += nr * f.x;
            acc[2 * w + 1] += nr * f.y;
        }
#pragma unroll
        for (int w = 0; w < 4; w++) {
            float2 f = __half22float2(p1[w]);
            acc[8 + 2 * w + 0] += nr * f.x;
            acc[8 + 2 * w + 1] += nr * f.y;
        }
    }
#pragma unroll
    for (int o = 16; o; o >>= 1) {
#pragma unroll
        for (int k = 0; k < F; k++) acc[k] += __shfl_xor_sync(0xffffffffu, acc[k], o);
    }
    int g = __ldg(&batch[n]);
    if (lane == 16) atomicAdd(&d_gcnt[g], 1);
    if (lane == 17) d_cnt[n] = 0;      // restore invariant for next launch
    if (lane < F) {
        int j = lane;
        float ci = 1.0f / (float)(cnt > 0 ? cnt : 1);
        float2 zea = d_zea[n];
        float aggr = zea.x * __ldg(&Wn2[16 * F + j]) + zea.y * __ldg(&Wn2[17 * F + j]);
#pragma unroll
        for (int k = 0; k < F; k++) aggr += acc[k] * __ldg(&Wn2[k * F + j]);
        aggr *= ci;
        float cent = __ldg(&bc2[j]);
        const float* hn = &d_h[n * F];
#pragma unroll
        for (int k = 0; k < F; k++) cent += hn[k] * __ldg(&Wc2[k * F + j]);
        float v = fmaxf(cent + aggr, 0.0f);
        atomicAdd(&d_gsum[g * F + j], v);
    }
}

// head MLP (mean + 2-layer MLP); re-zeroes d_gsum/d_gcnt/d_total
__global__ void k_head(const float* __restrict__ Wl1, const float* __restrict__ bl1,
                       const float* __restrict__ Wl2, const float* __restrict__ bl2,
                       float* __restrict__ out) {
    int g = threadIdx.x;
    if (g >= N_GRAPHS) return;
    if (g == 0) d_total = 0;           // restore invariant for next launch
    int c = d_gcnt[g];
    d_gcnt[g] = 0;
    float inv = 1.0f / (float)(c > 0 ? c : 1);
    float gm[F];
#pragma unroll
    for (int k = 0; k < F; k++) {
        gm[k] = d_gsum[g * F + k] * inv;
        d_gsum[g * F + k] = 0.0f;
    }
    float t[F];
#pragma unroll
    for (int j = 0; j < F; j++) {
        float a = bl1[j];
#pragma unroll
        for (int k = 0; k < F; k++) a += gm[k] * Wl1[k * F + j];
        t[j] = fmaxf(a, 0.0f);
    }
#pragma unroll
    for (int o = 0; o < 2; o++) {
        float a = bl2[o];
#pragma unroll
        for (int j = 0; j < F; j++) a += t[j] * Wl2[j * 2 + o];
        out[g * 2 + o] = a;
    }
}

// ---------------- launch ----------------
extern "C" void kernel_launch(void* const* d_in, const int* in_sizes, int n_in,
                              void* d_out, int out_size) {
    const float* x     = (const float*)d_in[0];
    const int*   ei    = (const int*)d_in[1];
    const float* ea    = (const float*)d_in[2];
    const int*   batch = (const int*)d_in[3];
    const float* Wc1 = (const float*)d_in[4];
    const float* bc1 = (const float*)d_in[5];
    const float* Wn1 = (const float*)d_in[6];
    const float* Wc2 = (const float*)d_in[7];
    const float* bc2 = (const float*)d_in[8];
    const float* Wn2 = (const float*)d_in[9];
    const float* Wl1 = (const float*)d_in[10];
    const float* bl1 = (const float*)d_in[11];
    const float* Wl2 = (const float*)d_in[12];
    const float* bl2 = (const float*)d_in[13];
    float* out = (float*)d_out;

    const int T = 256;
    int eb4 = (N_EDGES / 4 + T - 1) / T;   // 4 edges per thread
    int wb = (N_NODES * 32 + T - 1) / T;   // warp-per-node grids (=12500)

    k_hist<<<eb4, T>>>(ei);
    k_off<<<NB, T>>>(x);
    k_scatter<<<eb4, T>>>(ei, ea);
    k_pull1<<<wb, T>>>(Wn1, Wc1, bc1);
    k_pull2<<<wb, T>>>(Wn2, Wc2, bc2, batch);
    k_head<<<1, 64>>>(Wl1, bl1, Wl2, bl2, out);
}